// round 9
// baseline (speedup 1.0000x reference)
#include <cuda_runtime.h>

// Binarization (braq high_order_residual, ORDER=2)
// x: (11008,4096) f32, mask: (11008,4096) int32 (0/1), out: (11008,4096) f32
//
// One block (512 threads) per row; each thread owns 8 elements (2 float4).
// Ungated inner passes + closed-form unmasked-lane corrections (U terms).
// c1 and c2 cached in registers; output uses out = (c1 - c2) + d2 + mean1.

static constexpr int ROWS    = 11008;
static constexpr int COLS    = 4096;
static constexpr int THREADS = 512;
static constexpr int VEC     = COLS / (THREADS * 4);   // 2 float4 per thread

// reduce two floats across the block in one barrier round
__device__ __forceinline__ float2 block_reduce2(float a, float b, float2* sh) {
    #pragma unroll
    for (int o = 16; o > 0; o >>= 1) {
        a += __shfl_down_sync(0xffffffffu, a, o);
        b += __shfl_down_sync(0xffffffffu, b, o);
    }
    const int lane = threadIdx.x & 31;
    const int wid  = threadIdx.x >> 5;
    if (lane == 0) sh[wid] = make_float2(a, b);
    __syncthreads();
    if (wid == 0) {
        float2 v = (lane < (THREADS / 32)) ? sh[lane] : make_float2(0.f, 0.f);
        a = v.x; b = v.y;
        #pragma unroll
        for (int o = 8; o > 0; o >>= 1) {
            a += __shfl_down_sync(0xffffffffu, a, o);
            b += __shfl_down_sync(0xffffffffu, b, o);
        }
        if (lane == 0) sh[0] = make_float2(a, b);
    }
    __syncthreads();
    float2 r = sh[0];
    __syncthreads();
    return r;
}

__global__ void __launch_bounds__(THREADS, 2)
binarize_kernel(const float4* __restrict__ x,
                const int4*   __restrict__ mask,
                float4*       __restrict__ out) {
    __shared__ float2 sh[THREADS / 32];

    const size_t base = (size_t)blockIdx.x * (COLS / 4);
    const float4* xr   = x    + base;
    const int4*   mr   = mask + base;
    float4*       orow = out  + base;

    float t[VEC][4];          // xm, then c1
    float t2[VEC][4];         // c2 (pass B)
    unsigned int mk = 0;      // VEC*4 = 8 mask bits

    // ---- pass 0: load, masked values, sum, count ----
    float s = 0.0f;
    #pragma unroll
    for (int j = 0; j < VEC; j++) {
        const int idx = threadIdx.x + j * THREADS;
        const float4 xv = __ldcs(&xr[idx]);
        const int4   mv = __ldcs(&mr[idx]);
        float v0 = mv.x ? xv.x : 0.0f; if (mv.x) mk |= 1u << (j * 4 + 0);
        float v1 = mv.y ? xv.y : 0.0f; if (mv.y) mk |= 1u << (j * 4 + 1);
        float v2 = mv.z ? xv.z : 0.0f; if (mv.z) mk |= 1u << (j * 4 + 2);
        float v3 = mv.w ? xv.w : 0.0f; if (mv.w) mk |= 1u << (j * 4 + 3);
        t[j][0] = v0; t[j][1] = v1; t[j][2] = v2; t[j][3] = v3;
        s += (v0 + v1) + (v2 + v3);
    }
    const float cthr = (float)__popc(mk);

    const float2 r0   = block_reduce2(s, cthr, sh);
    const float  sum1 = r0.x;
    const float  cnt  = r0.y;
    const float  inv  = 1.0f / fmaxf(cnt, 1.0f);
    const float  mean1 = sum1 * inv;                 // cnt==0 -> 0
    const float  U    = (float)COLS - cnt;           // unmasked count (row)

    // ---- pass A (ungated): a1 = sum|c1|, sg = sum sign(c1); cache c1 ----
    float a1 = 0.0f, sg = 0.0f;
    #pragma unroll
    for (int j = 0; j < VEC; j++) {
        #pragma unroll
        for (int e = 0; e < 4; e++) {
            const float c1 = t[j][e] - mean1;
            t[j][e] = c1;
            a1 += fabsf(c1);
            if (c1 > 0.0f) sg += 1.0f; else if (c1 < 0.0f) sg -= 1.0f;
        }
    }
    const float2 rA = block_reduce2(a1, sg, sh);

    // corrections: unmasked lane has c1 = -mean1
    const float sgn1   = (mean1 > 0.0f) ? 1.0f : ((mean1 < 0.0f) ? -1.0f : 0.0f);
    const float scale1 = (rA.x - U * fabsf(mean1)) * inv;
    const float sgm    = rA.y + U * sgn1;
    const float mean2  = -scale1 * sgm * inv;        // since sum_mask(c1) == 0

    // unmasked residual2 constant and its pass-B contribution
    const float r2u = -mean1 + sgn1 * scale1;
    const float K   = fabsf(r2u - mean2);

    // ---- pass B (ungated): c2 = (c1 - sign(c1)*scale1) - mean2; a2 = sum|c2| ----
    float a2 = 0.0f;
    #pragma unroll
    for (int j = 0; j < VEC; j++) {
        #pragma unroll
        for (int e = 0; e < 4; e++) {
            const float c1 = t[j][e];
            const float d  = (c1 > 0.0f) ? scale1 : ((c1 < 0.0f) ? -scale1 : 0.0f);
            const float c2 = (c1 - d) - mean2;
            t2[j][e] = c2;
            a2 += fabsf(c2);
        }
    }
    const float2 rB = block_reduce2(a2, 0.0f, sh);
    const float scale2 = (rB.x - U * K) * inv;

    // ---- output: out = (c1 - c2) + sign(c2)*scale2 + mean1 inside mask ----
    // (c1 - c2 == sign(c1)*scale1 + mean2, so this equals binary1 + binary2)
    #pragma unroll
    for (int j = 0; j < VEC; j++) {
        const int idx = threadIdx.x + j * THREADS;
        float4 o;
        float* op = &o.x;
        #pragma unroll
        for (int e = 0; e < 4; e++) {
            const float c1 = t[j][e];
            const float c2 = t2[j][e];
            const float d2 = (c2 > 0.0f) ? scale2 : ((c2 < 0.0f) ? -scale2 : 0.0f);
            const float v  = ((c1 - c2) + d2) + mean1;
            op[e] = (mk & (1u << (j * 4 + e))) ? v : 0.0f;
        }
        __stcs(&orow[idx], o);
    }
}

extern "C" void kernel_launch(void* const* d_in, const int* in_sizes, int n_in,
                              void* d_out, int out_size) {
    const float4* x = (const float4*)d_in[0];
    const int4*   m = (const int4*)d_in[1];
    float4*       o = (float4*)d_out;
    binarize_kernel<<<ROWS, THREADS>>>(x, m, o);
}